// round 13
// baseline (speedup 1.0000x reference)
#include <cuda_runtime.h>
#include <cuda_bf16.h>
#include <math_constants.h>

// MASS_18897856102446: fused weighted-sq-dist attention
// out[b,n] = out_dist[b,n] * softmax_n(-(att_dist[b,n]*mask[b,n]))
// B=1024, N=200, E=128 (fp32). HBM-bound: m + m_c = ~210MB streamed once.
// R13: cp.async pipeline widened to 5 warps/CTA (160 thr) -> 35 warps/SM at
//      7 CTAs/SM single wave (was 28). Chunk = 10 rows (2/warp), 20 exact
//      chunks, DEPTH=2 ring (20KB), two barriers per chunk. Regs must stay
//      <=58 for 7 CTAs/SM.

constexpr int N_     = 200;
constexpr int E_     = 128;
constexpr int NWARP  = 5;
constexpr int NTHR   = NWARP * 32;     // 160
constexpr int CH     = 10;             // rows per chunk
constexpr int NCHUNK = N_ / CH;        // 20 (exact)
constexpr int DEPTH  = 2;              // pipeline stages
constexpr int ROWB   = E_ * 4;         // 512 B per row
constexpr int CHUNKB = 2 * CH * ROWB;  // 10240 B per stage
constexpr int CHSTEP = CH * (E_ / 4);  // float4s per tensor per chunk (320)
constexpr int PIECES = 2 * CH * 32;    // 640 16B pieces per chunk
constexpr int PPT    = PIECES / NTHR;  // 4 pieces per thread

__global__ __launch_bounds__(NTHR, 7)
void mass_kernel(const float* __restrict__ q,
                 const float* __restrict__ q_p,
                 const float* __restrict__ m,
                 const float* __restrict__ m_c,
                 const float* __restrict__ A1,
                 const float* __restrict__ A2,
                 const float* __restrict__ biases,
                 const float* __restrict__ mask,
                 float* __restrict__ out)
{
    const int b    = blockIdx.x;
    const int tid  = threadIdx.x;
    const int warp = tid >> 5;
    const int lane = tid & 31;

    __shared__ __align__(16) char s_buf[DEPTH * CHUNKB];   // 20 KB ring
    __shared__ float4 s_v[E_ / 4], s_m2u[E_ / 4];
    __shared__ float  s_cq[4];
    __shared__ float  s_logit[N_], s_outd[N_];
    __shared__ float  s_b2[N_], s_mk[N_];
    __shared__ float  s_red[NWARP];

    const float4* __restrict__ m4 = reinterpret_cast<const float4*>(m   + (size_t)b * N_ * E_);
    const float4* __restrict__ c4 = reinterpret_cast<const float4*>(m_c + (size_t)b * N_ * E_);

    const unsigned sbase = (unsigned)__cvta_generic_to_shared(s_buf);

    // Hoisted per-thread copy descriptors (chunk-invariant).
    // piece p = i*160 + tid in [0,640): rowidx = p>>5 (0..19), tensor = rowidx>=10,
    // row = rowidx%10, ln = p&31.
    const float4* srcb[PPT];
    unsigned      dsto[PPT];
    #pragma unroll
    for (int i = 0; i < PPT; i++) {
        const int p      = i * NTHR + tid;
        const int ridx   = p >> 5;
        const int tensor = ridx >= CH;
        const int row    = tensor ? ridx - CH : ridx;
        const int ln     = p & 31;
        srcb[i] = (tensor ? c4 : m4) + row * (E_ / 4) + ln;
        dsto[i] = sbase + tensor * (CH * ROWB) + row * ROWB + ln * 16;
    }

    auto issue_chunk = [&](int k, int slot) {
        const unsigned sb = slot * CHUNKB;
        const int      ks = k * CHSTEP;
        #pragma unroll
        for (int i = 0; i < PPT; i++) {
            asm volatile("cp.async.cg.shared.global [%0], [%1], 16;"
                         :: "r"(dsto[i] + sb), "l"(srcb[i] + ks) : "memory");
        }
        asm volatile("cp.async.commit_group;" ::: "memory");
    };

    // Prime chunks 0 and 1 BEFORE the prologue (DRAM latency hides it).
    issue_chunk(0, 0);
    issue_chunk(1, 1);

    // Prologue: stage v, m2u, Cq, 2*bias, mask. (128 threads cover E_.)
    if (tid < E_) {
        const float a1 = A1[tid];
        const float a2 = A2[tid];
        const float a1s = a1 * a1, a2s = a2 * a2;
        const float qv  = q  [(size_t)b * E_ + tid];
        const float qpv = q_p[(size_t)b * E_ + tid];
        reinterpret_cast<float*>(s_v)  [tid] = a1s + a2s;
        reinterpret_cast<float*>(s_m2u)[tid] = -2.f * (a1s * qv + a2s * qpv);

        float c = a1s * qv * qv + a2s * qpv * qpv;
        #pragma unroll
        for (int o = 16; o; o >>= 1)
            c += __shfl_xor_sync(0xffffffffu, c, o);
        if (lane == 0) s_cq[warp] = c;   // warps 0..3
    }
    {
        s_b2[tid] = 2.f * biases[(size_t)b * N_ + tid];
        s_mk[tid] = mask  [(size_t)b * N_ + tid];
        if (tid + NTHR < N_) {
            s_b2[tid + NTHR] = 2.f * biases[(size_t)b * N_ + tid + NTHR];
            s_mk[tid + NTHR] = mask  [(size_t)b * N_ + tid + NTHR];
        }
    }
    __syncthreads();

    const float4 vv = s_v[lane];
    const float4 mu = s_m2u[lane];
    const float  Cq = s_cq[0] + s_cq[1] + s_cq[2] + s_cq[3];

    auto body = [&](const float4 mv, const float4 cv, float& sa, float& so) {
        float t;
        t = fmaf(vv.x, mv.x, mu.x); sa = mv.x * t;
        t = fmaf(vv.y, mv.y, mu.y); sa = fmaf(mv.y, t, sa);
        t = fmaf(vv.z, mv.z, mu.z); sa = fmaf(mv.z, t, sa);
        t = fmaf(vv.w, mv.w, mu.w); sa = fmaf(mv.w, t, sa);
        t = fmaf(vv.x, cv.x, mu.x); so = cv.x * t;
        t = fmaf(vv.y, cv.y, mu.y); so = fmaf(cv.y, t, so);
        t = fmaf(vv.z, cv.z, mu.z); so = fmaf(cv.z, t, so);
        t = fmaf(vv.w, cv.w, mu.w); so = fmaf(cv.w, t, so);
    };

    const unsigned FULL = 0xffffffffu;
    const bool lo16 = (lane & 16) == 0;
    const bool b3z  = (lane & 8)  == 0;

    // Pipeline, DEPTH=2, two barriers per chunk:
    //   wait chunk k -> bar (visibility) -> compute k -> bar (slot free)
    //   -> issue chunk k+2 into slot k%2.
    #pragma unroll 1
    for (int k = 0; k < NCHUNK; k++) {
        const int slot = k & 1;
        asm volatile("cp.async.wait_group 1;" ::: "memory");
        __syncthreads();

        const char* buf = s_buf + slot * CHUNKB;
        const int r0 = 2 * warp;
        const int r1 = 2 * warp + 1;
        const float4 mv0 = reinterpret_cast<const float4*>(buf + r0 * ROWB)[lane];
        const float4 cv0 = reinterpret_cast<const float4*>(buf + CH * ROWB + r0 * ROWB)[lane];
        const float4 mv1 = reinterpret_cast<const float4*>(buf + r1 * ROWB)[lane];
        const float4 cv1 = reinterpret_cast<const float4*>(buf + CH * ROWB + r1 * ROWB)[lane];

        float sa0, so0, sa1, so1;
        body(mv0, cv0, sa0, so0);
        body(mv1, cv1, sa1, so1);

        // Pair-merging tree: 4 warp-sums in 9 shuffles.
        float A, B;
        A = sa0 + __shfl_xor_sync(FULL, sa0, 16);
        B = so0 + __shfl_xor_sync(FULL, so0, 16);
        const float t0 = lo16 ? A : B;
        A = sa1 + __shfl_xor_sync(FULL, sa1, 16);
        B = so1 + __shfl_xor_sync(FULL, so1, 16);
        const float t1 = lo16 ? A : B;

        A = t0 + __shfl_xor_sync(FULL, t0, 8);
        B = t1 + __shfl_xor_sync(FULL, t1, 8);
        float s = b3z ? A : B;

        s += __shfl_xor_sync(FULL, s, 4);
        s += __shfl_xor_sync(FULL, s, 2);
        s += __shfl_xor_sync(FULL, s, 1);

        if ((lane & 7) == 0) {
            const int row = (lane >> 3) & 1;
            const int n   = k * CH + 2 * warp + row;
            const float val = (s + Cq + s_b2[n]) * s_mk[n];
            if (lo16) s_logit[n] = -val;
            else      s_outd[n]  =  val;
        }

        __syncthreads();                 // slot free to overwrite
        const int kn = k + 2;
        if (kn < NCHUNK) {
            issue_chunk(kn, slot);
        } else {
            asm volatile("cp.async.commit_group;" ::: "memory");
        }
    }

    // Block softmax over N_=200 with 160 threads: covers tid and tid+160.
    const int  n2ok = (tid + NTHR) < N_;
    const float v1 = s_logit[tid];
    const float v2 = n2ok ? s_logit[tid + NTHR] : -CUDART_INF_F;

    float wm = fmaxf(v1, v2);
    #pragma unroll
    for (int o = 16; o; o >>= 1)
        wm = fmaxf(wm, __shfl_xor_sync(0xffffffffu, wm, o));
    if (lane == 0) s_red[warp] = wm;
    __syncthreads();

    float mx = s_red[0];
    #pragma unroll
    for (int i = 1; i < NWARP; i++) mx = fmaxf(mx, s_red[i]);

    const float ex1 = __expf(v1 - mx);
    const float ex2 = n2ok ? __expf(v2 - mx) : 0.f;

    float ws = ex1 + ex2;
    #pragma unroll
    for (int o = 16; o; o >>= 1)
        ws += __shfl_xor_sync(0xffffffffu, ws, o);
    __syncthreads();
    if (lane == 0) s_red[warp] = ws;
    __syncthreads();

    float tot = s_red[0];
    #pragma unroll
    for (int i = 1; i < NWARP; i++) tot += s_red[i];
    const float inv = 1.f / tot;

    out[(size_t)b * N_ + tid] = s_outd[tid] * ex1 * inv;
    if (n2ok)
        out[(size_t)b * N_ + tid + NTHR] = s_outd[tid + NTHR] * ex2 * inv;
}

extern "C" void kernel_launch(void* const* d_in, const int* in_sizes, int n_in,
                              void* d_out, int out_size)
{
    const float* q      = (const float*)d_in[0];
    const float* q_p    = (const float*)d_in[1];
    const float* m      = (const float*)d_in[2];
    const float* m_c    = (const float*)d_in[3];
    const float* A1     = (const float*)d_in[4];
    const float* A2     = (const float*)d_in[5];
    const float* biases = (const float*)d_in[6];
    const float* mask   = (const float*)d_in[7];
    float* out = (float*)d_out;

    const int B = in_sizes[0] / E_;   // 1024
    mass_kernel<<<B, NTHR>>>(q, q_p, m, m_c, A1, A2, biases, mask, out);
}

// round 14
// speedup vs baseline: 1.0077x; 1.0077x over previous
#include <cuda_runtime.h>
#include <cuda_bf16.h>
#include <math_constants.h>

// MASS_18897856102446: fused weighted-sq-dist attention
// out[b,n] = out_dist[b,n] * softmax_n(-(att_dist[b,n]*mask[b,n]))
// B=1024, N=200, E=128 (fp32). HBM-bound: m + m_c = ~210MB streamed once.
// R14: bulk-TMA pipeline. Each 8-row chunk of m / m_c is CONTIGUOUS (4KB), so
//      ONE cp.async.bulk per tensor per chunk (2 instrs, single thread)
//      replaces 640 LDGSTS. Completion via mbarrier expect_tx. DEPTH=3 ring,
//      25 chunks, 128 thr CTAs, single wave. Compute identical to R12.

constexpr int N_     = 200;
constexpr int E_     = 128;
constexpr int NWARP  = 4;
constexpr int NTHR   = NWARP * 32;     // 128
constexpr int CH     = 8;              // rows per chunk
constexpr int NCHUNK = N_ / CH;        // 25 (exact)
constexpr int DEPTH  = 3;              // pipeline stages
constexpr int ROWB   = E_ * 4;         // 512 B per row
constexpr int HALFB  = CH * ROWB;      // 4096 B per tensor per chunk
constexpr int CHUNKB = 2 * HALFB;      // 8192 B per stage

__global__ __launch_bounds__(NTHR, 7)
void mass_kernel(const float* __restrict__ q,
                 const float* __restrict__ q_p,
                 const float* __restrict__ m,
                 const float* __restrict__ m_c,
                 const float* __restrict__ A1,
                 const float* __restrict__ A2,
                 const float* __restrict__ biases,
                 const float* __restrict__ mask,
                 float* __restrict__ out)
{
    const int b    = blockIdx.x;
    const int tid  = threadIdx.x;
    const int warp = tid >> 5;
    const int lane = tid & 31;

    __shared__ __align__(16) char s_buf[DEPTH * CHUNKB];   // 24 KB ring
    __shared__ __align__(8)  unsigned long long s_mbar[DEPTH];
    __shared__ float4 s_v[E_ / 4], s_m2u[E_ / 4];
    __shared__ float  s_cq[NWARP];
    __shared__ float  s_logit[N_], s_outd[N_];
    __shared__ float  s_b2[N_], s_mk[N_];
    __shared__ float  s_red[NWARP];

    const char* __restrict__ mB = reinterpret_cast<const char*>(m   + (size_t)b * N_ * E_);
    const char* __restrict__ cB = reinterpret_cast<const char*>(m_c + (size_t)b * N_ * E_);

    const unsigned sbase = (unsigned)__cvta_generic_to_shared(s_buf);
    const unsigned mbase = (unsigned)__cvta_generic_to_shared(s_mbar);

    // Init mbarriers (count=1: satisfied by the issuing thread's expect_tx arrive).
    if (tid == 0) {
        #pragma unroll
        for (int s = 0; s < DEPTH; s++)
            asm volatile("mbarrier.init.shared.b64 [%0], 1;"
                         :: "r"(mbase + s * 8) : "memory");
    }
    __syncthreads();

    // Issue chunk k into slot: one expect_tx + two bulk copies, single thread.
    auto issue_chunk = [&](int k, int slot) {
        if (tid == 0) {
            const unsigned mb  = mbase + slot * 8;
            const unsigned dst = sbase + slot * CHUNKB;
            const size_t   off = (size_t)k * HALFB;
            asm volatile("mbarrier.arrive.expect_tx.shared.b64 _, [%0], %1;"
                         :: "r"(mb), "r"((unsigned)CHUNKB) : "memory");
            asm volatile("cp.async.bulk.shared::cta.global.mbarrier::complete_tx::bytes "
                         "[%0], [%1], %2, [%3];"
                         :: "r"(dst), "l"(mB + off), "r"((unsigned)HALFB), "r"(mb)
                         : "memory");
            asm volatile("cp.async.bulk.shared::cta.global.mbarrier::complete_tx::bytes "
                         "[%0], [%1], %2, [%3];"
                         :: "r"(dst + HALFB), "l"(cB + off), "r"((unsigned)HALFB), "r"(mb)
                         : "memory");
        }
    };

    // All-thread wait on stage barrier for given phase parity.
    auto mwait = [&](int slot, int ph) {
        const unsigned mb = mbase + slot * 8;
        asm volatile(
            "{\n\t.reg .pred P;\n\t"
            "WLP_%=:\n\t"
            "mbarrier.try_wait.parity.acquire.cta.shared::cta.b64 P, [%0], %1, 0x989680;\n\t"
            "@P bra.uni WDN_%=;\n\t"
            "bra.uni WLP_%=;\n\t"
            "WDN_%=:\n\t}"
            :: "r"(mb), "r"((unsigned)ph) : "memory");
    };

    // Prime chunks 0..2 BEFORE the prologue (DRAM latency hides it).
    issue_chunk(0, 0);
    issue_chunk(1, 1);
    issue_chunk(2, 2);

    // Prologue: stage v = a1^2+a2^2, m2u = -2(a1^2 q + a2^2 qp), Cq, 2*bias, mask.
    {
        const float a1 = A1[tid];
        const float a2 = A2[tid];
        const float a1s = a1 * a1, a2s = a2 * a2;
        const float qv  = q  [(size_t)b * E_ + tid];
        const float qpv = q_p[(size_t)b * E_ + tid];
        reinterpret_cast<float*>(s_v)  [tid] = a1s + a2s;
        reinterpret_cast<float*>(s_m2u)[tid] = -2.f * (a1s * qv + a2s * qpv);

        s_b2[tid] = 2.f * biases[(size_t)b * N_ + tid];
        s_mk[tid] = mask  [(size_t)b * N_ + tid];
        if (tid + NTHR < N_) {
            s_b2[tid + NTHR] = 2.f * biases[(size_t)b * N_ + tid + NTHR];
            s_mk[tid + NTHR] = mask  [(size_t)b * N_ + tid + NTHR];
        }

        float c = a1s * qv * qv + a2s * qpv * qpv;
        #pragma unroll
        for (int o = 16; o; o >>= 1)
            c += __shfl_xor_sync(0xffffffffu, c, o);
        if (lane == 0) s_cq[warp] = c;
    }
    __syncthreads();

    const float4 vv = s_v[lane];
    const float4 mu = s_m2u[lane];
    const float  Cq = s_cq[0] + s_cq[1] + s_cq[2] + s_cq[3];

    auto body = [&](const float4 mv, const float4 cv, float& sa, float& so) {
        float t;
        t = fmaf(vv.x, mv.x, mu.x); sa = mv.x * t;
        t = fmaf(vv.y, mv.y, mu.y); sa = fmaf(mv.y, t, sa);
        t = fmaf(vv.z, mv.z, mu.z); sa = fmaf(mv.z, t, sa);
        t = fmaf(vv.w, mv.w, mu.w); sa = fmaf(mv.w, t, sa);
        t = fmaf(vv.x, cv.x, mu.x); so = cv.x * t;
        t = fmaf(vv.y, cv.y, mu.y); so = fmaf(cv.y, t, so);
        t = fmaf(vv.z, cv.z, mu.z); so = fmaf(cv.z, t, so);
        t = fmaf(vv.w, cv.w, mu.w); so = fmaf(cv.w, t, so);
    };

    const unsigned FULL = 0xffffffffu;
    const bool lo16 = (lane & 16) == 0;
    const bool b3z  = (lane & 8)  == 0;

    // Pipeline: wait(k) -> compute k -> __syncthreads (all warps done with
    // slot) -> issue k+3 into the freed slot.
    #pragma unroll 1
    for (int k = 0; k < NCHUNK; k++) {
        const int slot = k % DEPTH;
        const int ph   = (k / DEPTH) & 1;
        mwait(slot, ph);

        const char* buf = s_buf + slot * CHUNKB;
        const int r0 = 2 * warp;
        const int r1 = 2 * warp + 1;
        const float4 mv0 = reinterpret_cast<const float4*>(buf + r0 * ROWB)[lane];
        const float4 cv0 = reinterpret_cast<const float4*>(buf + HALFB + r0 * ROWB)[lane];
        const float4 mv1 = reinterpret_cast<const float4*>(buf + r1 * ROWB)[lane];
        const float4 cv1 = reinterpret_cast<const float4*>(buf + HALFB + r1 * ROWB)[lane];

        float sa0, so0, sa1, so1;
        body(mv0, cv0, sa0, so0);
        body(mv1, cv1, sa1, so1);

        // Pair-merging tree: 4 warp-sums in 9 shuffles.
        float A, B;
        A = sa0 + __shfl_xor_sync(FULL, sa0, 16);
        B = so0 + __shfl_xor_sync(FULL, so0, 16);
        const float t0 = lo16 ? A : B;
        A = sa1 + __shfl_xor_sync(FULL, sa1, 16);
        B = so1 + __shfl_xor_sync(FULL, so1, 16);
        const float t1 = lo16 ? A : B;

        A = t0 + __shfl_xor_sync(FULL, t0, 8);
        B = t1 + __shfl_xor_sync(FULL, t1, 8);
        float s = b3z ? A : B;

        s += __shfl_xor_sync(FULL, s, 4);
        s += __shfl_xor_sync(FULL, s, 2);
        s += __shfl_xor_sync(FULL, s, 1);

        if ((lane & 7) == 0) {
            const int row = (lane >> 3) & 1;
            const int n   = k * CH + 2 * warp + row;
            const float val = (s + Cq + s_b2[n]) * s_mk[n];
            if (lo16) s_logit[n] = -val;
            else      s_outd[n]  =  val;
        }

        __syncthreads();                 // slot free to overwrite
        const int kn = k + DEPTH;
        if (kn < NCHUNK) issue_chunk(kn, slot);
    }

    // Block softmax over N_=200 with 128 threads.
    const int  n2ok = (tid + NTHR) < N_;
    const float v1 = s_logit[tid];
    const float v2 = n2ok ? s_logit[tid + NTHR] : -CUDART_INF_F;

    float wm = fmaxf(v1, v2);
    #pragma unroll
    for (int o = 16; o; o >>= 1)
        wm = fmaxf(wm, __shfl_xor_sync(0xffffffffu, wm, o));
    if (lane == 0) s_red[warp] = wm;
    __syncthreads();

    float mx = fmaxf(fmaxf(s_red[0], s_red[1]), fmaxf(s_red[2], s_red[3]));

    const float ex1 = __expf(v1 - mx);
    const float ex2 = n2ok ? __expf(v2 - mx) : 0.f;

    float ws = ex1 + ex2;
    #pragma unroll
    for (int o = 16; o; o >>= 1)
        ws += __shfl_xor_sync(0xffffffffu, ws, o);
    __syncthreads();
    if (lane == 0) s_red[warp] = ws;
    __syncthreads();

    const float inv = 1.f / (s_red[0] + s_red[1] + s_red[2] + s_red[3]);

    out[(size_t)b * N_ + tid] = s_outd[tid] * ex1 * inv;
    if (n2ok)
        out[(size_t)b * N_ + tid + NTHR] = s_outd[tid + NTHR] * ex2 * inv;
}

extern "C" void kernel_launch(void* const* d_in, const int* in_sizes, int n_in,
                              void* d_out, int out_size)
{
    const float* q      = (const float*)d_in[0];
    const float* q_p    = (const float*)d_in[1];
    const float* m      = (const float*)d_in[2];
    const float* m_c    = (const float*)d_in[3];
    const float* A1     = (const float*)d_in[4];
    const float* A2     = (const float*)d_in[5];
    const float* biases = (const float*)d_in[6];
    const float* mask   = (const float*)d_in[7];
    float* out = (float*)d_out;

    const int B = in_sizes[0] / E_;   // 1024
    mass_kernel<<<B, NTHR>>>(q, q_p, m, m_c, A1, A2, biases, mask, out);
}

// round 15
// speedup vs baseline: 1.0208x; 1.0130x over previous
#include <cuda_runtime.h>
#include <cuda_bf16.h>
#include <math_constants.h>

// MASS_18897856102446: fused weighted-sq-dist attention — FINAL (R10 confirm)
// out[b,n] = out_dist[b,n] * softmax_n(-(att_dist[b,n]*mask[b,n]))
// B=1024, N=200, E=128 (fp32). HBM-bound: m + m_c = ~210MB streamed once.
// Design: 128-thr CTAs, grid=1024 single wave (7 CTAs/SM); expanded-square
// algebra (16 FFMA/row, shared u/v/Cq for both tensors); 16-float4 front-
// batched load groups (max MLP under 72-reg budget); pair-merging tree
// reduction (31 SHFL / 16 sums); group-0 loads hoisted above the prologue.
// Measured: 36.9us wall / 35.5us kernel, 6.1 TB/s (ceiling confirmed across
// LDG / LDGSTS / bulk-TMA architectures in R11-R14).

constexpr int N_ = 200;
constexpr int E_ = 128;
constexpr int NWARP = 4;
constexpr int NTHR = NWARP * 32;   // 128

__global__ __launch_bounds__(NTHR, 7)
void mass_kernel(const float* __restrict__ q,
                 const float* __restrict__ q_p,
                 const float* __restrict__ m,
                 const float* __restrict__ m_c,
                 const float* __restrict__ A1,
                 const float* __restrict__ A2,
                 const float* __restrict__ biases,
                 const float* __restrict__ mask,
                 float* __restrict__ out)
{
    const int b    = blockIdx.x;
    const int tid  = threadIdx.x;
    const int warp = tid >> 5;
    const int lane = tid & 31;

    __shared__ float4 s_v[E_ / 4], s_m2u[E_ / 4];
    __shared__ float  s_cq[NWARP];
    __shared__ float  s_logit[N_], s_outd[N_];
    __shared__ float  s_b2[N_], s_mk[N_];
    __shared__ float  s_red[NWARP];

    const float4* __restrict__ m4 = reinterpret_cast<const float4*>(m   + (size_t)b * N_ * E_);
    const float4* __restrict__ c4 = reinterpret_cast<const float4*>(m_c + (size_t)b * N_ * E_);

    // ── Hoisted group-0 loads: in flight while the prologue runs. ──
    const int nb0 = warp;   // k = 0
    const float4 mv0 = m4[(nb0 + 0 * NWARP) * (E_ / 4) + lane];
    const float4 mv1 = m4[(nb0 + 1 * NWARP) * (E_ / 4) + lane];
    const float4 mv2 = m4[(nb0 + 2 * NWARP) * (E_ / 4) + lane];
    const float4 mv3 = m4[(nb0 + 3 * NWARP) * (E_ / 4) + lane];
    const float4 mv4 = m4[(nb0 + 4 * NWARP) * (E_ / 4) + lane];
    const float4 mv5 = m4[(nb0 + 5 * NWARP) * (E_ / 4) + lane];
    const float4 mv6 = m4[(nb0 + 6 * NWARP) * (E_ / 4) + lane];
    const float4 mv7 = m4[(nb0 + 7 * NWARP) * (E_ / 4) + lane];
    const float4 cv0 = c4[(nb0 + 0 * NWARP) * (E_ / 4) + lane];
    const float4 cv1 = c4[(nb0 + 1 * NWARP) * (E_ / 4) + lane];
    const float4 cv2 = c4[(nb0 + 2 * NWARP) * (E_ / 4) + lane];
    const float4 cv3 = c4[(nb0 + 3 * NWARP) * (E_ / 4) + lane];
    const float4 cv4 = c4[(nb0 + 4 * NWARP) * (E_ / 4) + lane];
    const float4 cv5 = c4[(nb0 + 5 * NWARP) * (E_ / 4) + lane];
    const float4 cv6 = c4[(nb0 + 6 * NWARP) * (E_ / 4) + lane];
    const float4 cv7 = c4[(nb0 + 7 * NWARP) * (E_ / 4) + lane];

    // ── Prologue (overlapped with in-flight group-0 loads). ──
    {
        const float a1 = A1[tid];
        const float a2 = A2[tid];
        const float a1s = a1 * a1, a2s = a2 * a2;
        const float qv  = q  [(size_t)b * E_ + tid];
        const float qpv = q_p[(size_t)b * E_ + tid];
        reinterpret_cast<float*>(s_v)  [tid] = a1s + a2s;
        reinterpret_cast<float*>(s_m2u)[tid] = -2.f * (a1s * qv + a2s * qpv);

        s_b2[tid] = 2.f * biases[(size_t)b * N_ + tid];
        s_mk[tid] = mask  [(size_t)b * N_ + tid];
        if (tid + NTHR < N_) {
            s_b2[tid + NTHR] = 2.f * biases[(size_t)b * N_ + tid + NTHR];
            s_mk[tid + NTHR] = mask  [(size_t)b * N_ + tid + NTHR];
        }

        float c = a1s * qv * qv + a2s * qpv * qpv;
        #pragma unroll
        for (int o = 16; o; o >>= 1)
            c += __shfl_xor_sync(0xffffffffu, c, o);
        if (lane == 0) s_cq[warp] = c;
    }
    __syncthreads();

    const float4 vv = s_v[lane];
    const float4 mu = s_m2u[lane];
    const float  Cq = s_cq[0] + s_cq[1] + s_cq[2] + s_cq[3];

    auto body = [&](const float4 mv, const float4 cv, float& sa, float& so) {
        float t;
        t = fmaf(vv.x, mv.x, mu.x); sa = mv.x * t;
        t = fmaf(vv.y, mv.y, mu.y); sa = fmaf(mv.y, t, sa);
        t = fmaf(vv.z, mv.z, mu.z); sa = fmaf(mv.z, t, sa);
        t = fmaf(vv.w, mv.w, mu.w); sa = fmaf(mv.w, t, sa);
        t = fmaf(vv.x, cv.x, mu.x); so = cv.x * t;
        t = fmaf(vv.y, cv.y, mu.y); so = fmaf(cv.y, t, so);
        t = fmaf(vv.z, cv.z, mu.z); so = fmaf(cv.z, t, so);
        t = fmaf(vv.w, cv.w, mu.w); so = fmaf(cv.w, t, so);
    };

    auto finish1 = [&](int n, float sa, float so) {
        #pragma unroll
        for (int o = 16; o; o >>= 1) {
            sa += __shfl_xor_sync(0xffffffffu, sa, o);
            so += __shfl_xor_sync(0xffffffffu, so, o);
        }
        if (lane == 0) {
            const float add = Cq + s_b2[n];
            const float mk  = s_mk[n];
            s_logit[n] = -((sa + add) * mk);
            s_outd[n]  = (so + add) * mk;
        }
    };

    const unsigned FULL = 0xffffffffu;
    const bool lo16 = (lane & 16) == 0;
    const bool b3z  = (lane & 8)  == 0;
    const bool b2z  = (lane & 4)  == 0;
    const bool b1z  = (lane & 2)  == 0;

    auto reduceG = [&](int nb,
                       float sa0, float so0, float sa1, float so1,
                       float sa2, float so2, float sa3, float so3,
                       float sa4, float so4, float sa5, float so5,
                       float sa6, float so6, float sa7, float so7) {
        float A, B;
        A = sa0 + __shfl_xor_sync(FULL, sa0, 16);
        B = so0 + __shfl_xor_sync(FULL, so0, 16);
        const float r0 = lo16 ? A : B;
        A = sa1 + __shfl_xor_sync(FULL, sa1, 16);
        B = so1 + __shfl_xor_sync(FULL, so1, 16);
        const float r1 = lo16 ? A : B;
        A = sa2 + __shfl_xor_sync(FULL, sa2, 16);
        B = so2 + __shfl_xor_sync(FULL, so2, 16);
        const float r2 = lo16 ? A : B;
        A = sa3 + __shfl_xor_sync(FULL, sa3, 16);
        B = so3 + __shfl_xor_sync(FULL, so3, 16);
        const float r3 = lo16 ? A : B;
        A = sa4 + __shfl_xor_sync(FULL, sa4, 16);
        B = so4 + __shfl_xor_sync(FULL, so4, 16);
        const float r4 = lo16 ? A : B;
        A = sa5 + __shfl_xor_sync(FULL, sa5, 16);
        B = so5 + __shfl_xor_sync(FULL, so5, 16);
        const float r5 = lo16 ? A : B;
        A = sa6 + __shfl_xor_sync(FULL, sa6, 16);
        B = so6 + __shfl_xor_sync(FULL, so6, 16);
        const float r6 = lo16 ? A : B;
        A = sa7 + __shfl_xor_sync(FULL, sa7, 16);
        B = so7 + __shfl_xor_sync(FULL, so7, 16);
        const float r7 = lo16 ? A : B;

        A = r0 + __shfl_xor_sync(FULL, r0, 8);
        B = r1 + __shfl_xor_sync(FULL, r1, 8);
        const float s0 = b3z ? A : B;
        A = r2 + __shfl_xor_sync(FULL, r2, 8);
        B = r3 + __shfl_xor_sync(FULL, r3, 8);
        const float s1 = b3z ? A : B;
        A = r4 + __shfl_xor_sync(FULL, r4, 8);
        B = r5 + __shfl_xor_sync(FULL, r5, 8);
        const float s2 = b3z ? A : B;
        A = r6 + __shfl_xor_sync(FULL, r6, 8);
        B = r7 + __shfl_xor_sync(FULL, r7, 8);
        const float s3 = b3z ? A : B;

        A = s0 + __shfl_xor_sync(FULL, s0, 4);
        B = s1 + __shfl_xor_sync(FULL, s1, 4);
        const float t0 = b2z ? A : B;
        A = s2 + __shfl_xor_sync(FULL, s2, 4);
        B = s3 + __shfl_xor_sync(FULL, s3, 4);
        const float t1 = b2z ? A : B;

        A = t0 + __shfl_xor_sync(FULL, t0, 2);
        B = t1 + __shfl_xor_sync(FULL, t1, 2);
        const float u = b1z ? A : B;

        const float f = u + __shfl_xor_sync(FULL, u, 1);

        if ((lane & 1) == 0) {
            const int row = 4 * ((lane >> 1) & 1) + 2 * ((lane >> 2) & 1)
                          + ((lane >> 3) & 1);
            const int n   = nb + row * NWARP;
            const float val = (f + Cq + s_b2[n]) * s_mk[n];
            if (lo16) s_logit[n] = -val;
            else      s_outd[n]  =  val;
        }
    };

    // ── Group 0 (preloaded) ──
    {
        float sa0, so0, sa1, so1, sa2, so2, sa3, so3;
        float sa4, so4, sa5, so5, sa6, so6, sa7, so7;
        body(mv0, cv0, sa0, so0);
        body(mv1, cv1, sa1, so1);
        body(mv2, cv2, sa2, so2);
        body(mv3, cv3, sa3, so3);
        body(mv4, cv4, sa4, so4);
        body(mv5, cv5, sa5, so5);
        body(mv6, cv6, sa6, so6);
        body(mv7, cv7, sa7, so7);
        reduceG(nb0, sa0, so0, sa1, so1, sa2, so2, sa3, so3,
                     sa4, so4, sa5, so5, sa6, so6, sa7, so7);
    }

    // ── Groups 1..5 ──
    #pragma unroll 1
    for (int k = 8; k < 48; k += 8) {
        const int nb = warp + k * NWARP;

        const float4 Mv0 = m4[(nb + 0 * NWARP) * (E_ / 4) + lane];
        const float4 Mv1 = m4[(nb + 1 * NWARP) * (E_ / 4) + lane];
        const float4 Mv2 = m4[(nb + 2 * NWARP) * (E_ / 4) + lane];
        const float4 Mv3 = m4[(nb + 3 * NWARP) * (E_ / 4) + lane];
        const float4 Mv4 = m4[(nb + 4 * NWARP) * (E_ / 4) + lane];
        const float4 Mv5 = m4[(nb + 5 * NWARP) * (E_ / 4) + lane];
        const float4 Mv6 = m4[(nb + 6 * NWARP) * (E_ / 4) + lane];
        const float4 Mv7 = m4[(nb + 7 * NWARP) * (E_ / 4) + lane];
        const float4 Cv0 = c4[(nb + 0 * NWARP) * (E_ / 4) + lane];
        const float4 Cv1 = c4[(nb + 1 * NWARP) * (E_ / 4) + lane];
        const float4 Cv2 = c4[(nb + 2 * NWARP) * (E_ / 4) + lane];
        const float4 Cv3 = c4[(nb + 3 * NWARP) * (E_ / 4) + lane];
        const float4 Cv4 = c4[(nb + 4 * NWARP) * (E_ / 4) + lane];
        const float4 Cv5 = c4[(nb + 5 * NWARP) * (E_ / 4) + lane];
        const float4 Cv6 = c4[(nb + 6 * NWARP) * (E_ / 4) + lane];
        const float4 Cv7 = c4[(nb + 7 * NWARP) * (E_ / 4) + lane];

        float sa0, so0, sa1, so1, sa2, so2, sa3, so3;
        float sa4, so4, sa5, so5, sa6, so6, sa7, so7;
        body(Mv0, Cv0, sa0, so0);
        body(Mv1, Cv1, sa1, so1);
        body(Mv2, Cv2, sa2, so2);
        body(Mv3, Cv3, sa3, so3);
        body(Mv4, Cv4, sa4, so4);
        body(Mv5, Cv5, sa5, so5);
        body(Mv6, Cv6, sa6, so6);
        body(Mv7, Cv7, sa7, so7);

        reduceG(nb, sa0, so0, sa1, so1, sa2, so2, sa3, so3,
                    sa4, so4, sa5, so5, sa6, so6, sa7, so7);
    }
    // Tail rows j = 48, 49.
    {
        const int n0 = warp + 48 * NWARP;
        const int n1 = warp + 49 * NWARP;
        const float4 Mv0 = m4[n0 * (E_ / 4) + lane];
        const float4 Mv1 = m4[n1 * (E_ / 4) + lane];
        const float4 Cv0 = c4[n0 * (E_ / 4) + lane];
        const float4 Cv1 = c4[n1 * (E_ / 4) + lane];
        float sa0, so0, sa1, so1;
        body(Mv0, Cv0, sa0, so0);
        body(Mv1, Cv1, sa1, so1);
        finish1(n0, sa0, so0);
        finish1(n1, sa1, so1);
    }
    __syncthreads();

    // Block softmax over N_=200 with 128 threads.
    const int  n2ok = (tid + NTHR) < N_;
    const float v1 = s_logit[tid];
    const float v2 = n2ok ? s_logit[tid + NTHR] : -CUDART_INF_F;

    float wm = fmaxf(v1, v2);
    #pragma unroll
    for (int o = 16; o; o >>= 1)
        wm = fmaxf(wm, __shfl_xor_sync(0xffffffffu, wm, o));
    if (lane == 0) s_red[warp] = wm;
    __syncthreads();

    float mx = fmaxf(fmaxf(s_red[0], s_red[1]), fmaxf(s_red[2], s_red[3]));

    const float ex1 = __expf(v1 - mx);
    const float ex2 = n2ok ? __expf(v2 - mx) : 0.f;

    float ws = ex1 + ex2;
    #pragma unroll
    for (int o = 16; o; o >>= 1)
        ws += __shfl_xor_sync(0xffffffffu, ws, o);
    __syncthreads();
    if (lane == 0) s_red[warp] = ws;
    __syncthreads();

    const float inv = 1.f / (s_red[0] + s_red[1] + s_red[2] + s_red[3]);

    out[(size_t)b * N_ + tid] = s_outd[tid] * ex1 * inv;
    if (n2ok)
        out[(size_t)b * N_ + tid + NTHR] = s_outd[tid + NTHR] * ex2 * inv;
}

extern "C" void kernel_launch(void* const* d_in, const int* in_sizes, int n_in,
                              void* d_out, int out_size)
{
    const float* q      = (const float*)d_in[0];
    const float* q_p    = (const float*)d_in[1];
    const float* m      = (const float*)d_in[2];
    const float* m_c    = (const float*)d_in[3];
    const float* A1     = (const float*)d_in[4];
    const float* A2     = (const float*)d_in[5];
    const float* biases = (const float*)d_in[6];
    const float* mask   = (const float*)d_in[7];
    float* out = (float*)d_out;

    const int B = in_sizes[0] / E_;   // 1024
    mass_kernel<<<B, NTHR>>>(q, q_p, m, m_c, A1, A2, biases, mask, out);
}